// round 5
// baseline (speedup 1.0000x reference)
#include <cuda_runtime.h>
#include <cuda_fp16.h>
#include <cstdint>
#include <cfloat>

// Shapes fixed by dataset: T=32768 tokens, K=4096 codes, D=256.
#define T_TOK 32768
#define K_COD 4096
#define D_DIM 256
#define EPS_GAP 0.01f

// Main kernel: CTA = 128 tokens x full K, 512 threads, warp grid 4(M) x 4(N),
// warp tile 32 tok x 32 codes. N chunk 128, k-stage 128 (8 HMMA k16 steps),
// 64 stages (32 chunks x 2 halves).
#define A_OFF   0        // A frags fp16: [mtile8][ktile16][lane] uint4 = 64KB
#define B_OFF   65536    // ring: 4 stages x 32KB ([kk8][np8][lane] uint4)
#define ESQ_OFF 196608   // 16KB
#define SMEM_BYTES 212992

__device__ uint4  g_at[(size_t)256 * 4096];   // 16MB packed A fragments
__device__ uint4  g_bt[(size_t)64 * 2048];    // 2MB packed B fragments
__device__ float  g_esq[K_COD];
__device__ float  g_cval[(size_t)T_TOK * 32];
__device__ int    g_cidx[(size_t)T_TOK * 32];

static __device__ __forceinline__ uint32_t smem_u32(const void* p) {
    uint32_t a;
    asm("{ .reg .u64 t; cvta.to.shared.u64 t, %1; cvt.u32.u64 %0, t; }"
        : "=r"(a) : "l"(p));
    return a;
}
static __device__ __forceinline__ void cp16(uint32_t dst, const void* src) {
    asm volatile("cp.async.cg.shared.global [%0], [%1], 16;"
                 :: "r"(dst), "l"(__cvta_generic_to_global(src)) : "memory");
}
#define CP_COMMIT() asm volatile("cp.async.commit_group;" ::: "memory")
#define CP_WAIT(n)  asm volatile("cp.async.wait_group %0;" :: "n"(n) : "memory")

static __device__ __forceinline__ void mma16(float& d0, float& d1, float& d2, float& d3,
                                             uint4 a, uint32_t b0, uint32_t b1) {
    asm volatile(
        "mma.sync.aligned.m16n8k16.row.col.f32.f16.f16.f32 "
        "{%0,%1,%2,%3}, {%4,%5,%6,%7}, {%8,%9}, {%0,%1,%2,%3};"
        : "+f"(d0), "+f"(d1), "+f"(d2), "+f"(d3)
        : "r"(a.x), "r"(a.y), "r"(a.z), "r"(a.w), "r"(b0), "r"(b1));
}
static __device__ __forceinline__ uint32_t h2pack(float a, float b) {
    __half2 h = __floats2half2_rn(a, b);
    return *(uint32_t*)&h;
}

// ---------------------------------------------------------------------------
__global__ void esq_kernel(const float* __restrict__ embed) {
    int k = blockIdx.x * blockDim.x + threadIdx.x;
    const float* row = embed + (size_t)k * D_DIM;
    float s = 0.f;
    for (int d = 0; d < D_DIM; ++d)
        s = __fadd_rn(s, __fmul_rn(row[d], row[d]));
    g_esq[k] = s;
}

// Pack x -> fp16 A fragments (m16n8k16 layout). Same layout as R4.
__global__ void pack_a_kernel(const float* __restrict__ x) {
    uint32_t u = blockIdx.x * 256 + threadIdx.x;
    int cta = u >> 12, r = u & 4095;
    int mtile = r >> 9, kt = (r >> 5) & 15, lane = r & 31;
    int row = cta * 128 + mtile * 16 + (lane >> 2);
    int col = kt * 16 + (lane & 3) * 2;
    const float* x0 = x + (size_t)row * D_DIM + col;
    const float* x8 = x0 + 8 * D_DIM;
    uint4 q;
    q.x = h2pack(x0[0], x0[1]);
    q.y = h2pack(x8[0], x8[1]);
    q.z = h2pack(x0[8], x0[9]);
    q.w = h2pack(x8[8], x8[9]);
    g_at[u] = q;
}

// Pack embed -> fp16 B fragments, paired for LDS.128. Layout identical to R4:
// unit u = [stage(64)][kk(8)][np(8)][lane(32)]; pair np covers codes
// n = nc*128 + np*16 + {0,8} + (lane>>2); k = half*128 + kk*16 + (lane%4)*2.
__global__ void pack_b_kernel(const float* __restrict__ embed) {
    uint32_t u = blockIdx.x * 256 + threadIdx.x;
    int s = u >> 11, r = u & 2047;
    int kk = r >> 8, np = (r >> 5) & 7, lane = r & 31;
    int nc = s >> 1, half = s & 1;
    int k = half * 128 + kk * 16 + (lane & 3) * 2;
    int n0 = nc * 128 + np * 16 + (lane >> 2);
    const float* e0 = embed + (size_t)n0 * D_DIM + k;
    const float* e1 = e0 + 8 * D_DIM;
    uint4 q;
    q.x = h2pack(e0[0], e0[1]);
    q.y = h2pack(e0[8], e0[9]);
    q.z = h2pack(e1[0], e1[1]);
    q.w = h2pack(e1[8], e1[9]);
    g_bt[u] = q;
}

// ---------------------------------------------------------------------------
// Main: fp16 GEMM scores + branchless per-source top-2. 512 threads.
__global__ __launch_bounds__(512, 1) void vq_mma_kernel() {
    extern __shared__ char sm[];
    const uint32_t sb = smem_u32(sm);
    const int tid = threadIdx.x, lane = tid & 31, wid = tid >> 5;
    const int warpM = wid & 3, warpN = wid >> 2;
    const int cta = blockIdx.x;

    // Prologue: A (64KB) + esq (16KB) + stages 0,1,2
    {
        const uint4* as = g_at + (size_t)cta * 4096;
#pragma unroll
        for (int i = 0; i < 8; ++i)
            cp16(sb + A_OFF + (uint32_t)(i * 512 + tid) * 16, as + i * 512 + tid);
        const uint4* es = (const uint4*)g_esq;
#pragma unroll
        for (int i = 0; i < 2; ++i)
            cp16(sb + ESQ_OFF + (uint32_t)(i * 512 + tid) * 16, es + i * 512 + tid);
#pragma unroll
        for (int i = 0; i < 4; ++i)
            cp16(sb + B_OFF + (uint32_t)(i * 512 + tid) * 16, g_bt + i * 512 + tid);
        CP_COMMIT();
#pragma unroll
        for (int i = 0; i < 4; ++i)
            cp16(sb + B_OFF + 32768 + (uint32_t)(i * 512 + tid) * 16,
                 g_bt + 2048 + i * 512 + tid);
        CP_COMMIT();
#pragma unroll
        for (int i = 0; i < 4; ++i)
            cp16(sb + B_OFF + 65536 + (uint32_t)(i * 512 + tid) * 16,
                 g_bt + 4096 + i * 512 + tid);
        CP_COMMIT();
    }

    float acc[2][4][4];
#pragma unroll
    for (int mt = 0; mt < 2; ++mt)
#pragma unroll
        for (int nt = 0; nt < 4; ++nt)
#pragma unroll
            for (int c = 0; c < 4; ++c) acc[mt][nt][c] = 0.f;

    float t1[4], t2[4];
    int   i1[4], i2[4];
#pragma unroll
    for (int s = 0; s < 4; ++s) {
        t1[s] = -FLT_MAX; t2[s] = -FLT_MAX; i1[s] = 0; i2[s] = 0;
    }

    const float* esm = (const float*)(sm + ESQ_OFF);

#pragma unroll 2
    for (int g = 0; g < 64; ++g) {
        CP_WAIT(2);
        __syncthreads();
        if (g + 3 < 64) {
            const uint4* bs = g_bt + (size_t)(g + 3) * 2048;
            uint32_t bd = sb + B_OFF + (uint32_t)((g + 3) & 3) * 32768;
#pragma unroll
            for (int i = 0; i < 4; ++i)
                cp16(bd + (uint32_t)(i * 512 + tid) * 16, bs + i * 512 + tid);
        }
        CP_COMMIT();

        const char* bbuf = sm + B_OFF + (g & 3) * 32768;
#pragma unroll
        for (int kk = 0; kk < 8; ++kk) {
            int ktile = (g & 1) * 8 + kk;
            uint4 a0 = *(const uint4*)(sm + A_OFF +
                       (size_t)(((warpM * 2 + 0) * 16 + ktile) * 32 + lane) * 16);
            uint4 a1 = *(const uint4*)(sm + A_OFF +
                       (size_t)(((warpM * 2 + 1) * 16 + ktile) * 32 + lane) * 16);
#pragma unroll
            for (int ntp = 0; ntp < 2; ++ntp) {
                uint4 bq = *(const uint4*)(bbuf +
                           (size_t)((kk * 8 + warpN * 2 + ntp) * 32 + lane) * 16);
                int ne = 2 * ntp, no = 2 * ntp + 1;
                mma16(acc[0][ne][0], acc[0][ne][1], acc[0][ne][2], acc[0][ne][3], a0, bq.x, bq.y);
                mma16(acc[1][ne][0], acc[1][ne][1], acc[1][ne][2], acc[1][ne][3], a1, bq.x, bq.y);
                mma16(acc[0][no][0], acc[0][no][1], acc[0][no][2], acc[0][no][3], a0, bq.z, bq.w);
                mma16(acc[1][no][0], acc[1][no][1], acc[1][no][2], acc[1][no][3], a1, bq.z, bq.w);
            }
        }

        if (g & 1) {
            // Chunk nc done: score = 2*dot - esq. 8 distinct codes per thread.
            int nc = g >> 1;
            int n0 = nc * 128 + warpN * 32 + (lane & 3) * 2;
            float2 es2[4];
#pragma unroll
            for (int nt = 0; nt < 4; ++nt)
                es2[nt] = *(const float2*)(esm + n0 + nt * 8);
#pragma unroll
            for (int mt = 0; mt < 2; ++mt)
#pragma unroll
                for (int nt = 0; nt < 4; ++nt)
#pragma unroll
                    for (int c = 0; c < 4; ++c) {
                        int n = n0 + nt * 8 + (c & 1);
                        float es = (c & 1) ? es2[nt].y : es2[nt].x;
                        float v = fmaf(2.f, acc[mt][nt][c], -es);
                        acc[mt][nt][c] = 0.f;
                        const int s = mt * 2 + (c >> 1);
                        bool gt1 = v > t1[s];
                        bool gt2 = v > t2[s];
                        i2[s] = gt1 ? i1[s] : (gt2 ? n : i2[s]);
                        t2[s] = gt1 ? t1[s] : (gt2 ? v : t2[s]);
                        i1[s] = gt1 ? n : i1[s];
                        t1[s] = gt1 ? v : t1[s];
                    }
        }
        __syncthreads();
    }

    // Write candidates: 16 sources x top-2 per token = 32.
    // Source slot = warpN*8 + (lane&3)*2 + {0,1}.
#pragma unroll
    for (int s = 0; s < 4; ++s) {
        int row = (warpM * 2 + (s >> 1)) * 16 + (s & 1) * 8 + (lane >> 2);
        size_t base = ((size_t)cta * 128 + row) * 32 + warpN * 8 + (lane & 3) * 2;
        g_cval[base + 0] = t1[s]; g_cidx[base + 0] = i1[s];
        g_cval[base + 1] = t2[s]; g_cidx[base + 1] = i2[s];
    }
}

// ---------------------------------------------------------------------------
// Merge + rare exact rescore + gather. One warp per token (32 candidates).
__global__ __launch_bounds__(256) void merge_kernel(const float* __restrict__ x,
                                                    const float* __restrict__ embed,
                                                    float* __restrict__ out_q,
                                                    float* __restrict__ out_i) {
    const int lane = threadIdx.x & 31, wid = threadIdx.x >> 5;
    const int t = blockIdx.x * 8 + wid;

    float v = g_cval[(size_t)t * 32 + lane];
    int   i = g_cidx[(size_t)t * 32 + lane];

    float v1 = v; int i1 = i;
#pragma unroll
    for (int off = 16; off > 0; off >>= 1) {
        float ov = __shfl_xor_sync(0xffffffffu, v1, off);
        int   oi = __shfl_xor_sync(0xffffffffu, i1, off);
        if (ov > v1 || (ov == v1 && oi < i1)) { v1 = ov; i1 = oi; }
    }
    float w = (i == i1) ? -FLT_MAX : v;
#pragma unroll
    for (int off = 16; off > 0; off >>= 1) {
        float ow = __shfl_xor_sync(0xffffffffu, w, off);
        if (ow > w) w = ow;
    }

    int best = i1;
    if (!(v1 - w >= EPS_GAP)) {
        // Exact fp32 rescore of the 32 candidates, ref-faithful rounding.
        const float* xr = x + (size_t)t * D_DIM;
        float p = 0.f;
#pragma unroll
        for (int j = 0; j < 8; ++j) {
            float xv = xr[lane + 32 * j];
            p = __fadd_rn(p, __fmul_rn(xv, xv));
        }
#pragma unroll
        for (int off = 16; off > 0; off >>= 1)
            p = __fadd_rn(p, __shfl_xor_sync(0xffffffffu, p, off));
        const float xsq = p;

        const float* er = embed + (size_t)i * D_DIM;
        float dot = 0.f;
        for (int d = 0; d < D_DIM; ++d)
            dot = fmaf(xr[d], er[d], dot);
        float t2v = __fsub_rn(xsq, __fmul_rn(2.f, dot));
        float dn = -__fadd_rn(t2v, g_esq[i]);

        float bv = dn; int bi = i;
#pragma unroll
        for (int off = 16; off > 0; off >>= 1) {
            float ov = __shfl_xor_sync(0xffffffffu, bv, off);
            int   oi = __shfl_xor_sync(0xffffffffu, bi, off);
            if (ov > bv || (ov == bv && oi < bi)) { bv = ov; bi = oi; }
        }
        best = bi;
    }

    const float4* src = (const float4*)(embed + (size_t)best * D_DIM);
    float4* dst = (float4*)(out_q + (size_t)t * D_DIM);
    dst[lane] = src[lane];
    dst[lane + 32] = src[lane + 32];
    if (lane == 0 && out_i) out_i[t] = (float)best;
}

// ---------------------------------------------------------------------------
extern "C" void kernel_launch(void* const* d_in, const int* in_sizes, int n_in,
                              void* d_out, int out_size) {
    const float* x     = (const float*)d_in[0];
    const float* embed = (const float*)d_in[1];

    int T = in_sizes[2];  // 32768

    float* outq = (float*)d_out;
    float* outi = nullptr;
    if ((long long)out_size >= (long long)T * D_DIM + T)
        outi = outq + (size_t)T * D_DIM;

    esq_kernel<<<K_COD / 256, 256>>>(embed);
    pack_b_kernel<<<(64 * 2048) / 256, 256>>>(embed);
    pack_a_kernel<<<(256 * 4096) / 256, 256>>>(x);

    cudaFuncSetAttribute(vq_mma_kernel,
                         cudaFuncAttributeMaxDynamicSharedMemorySize, SMEM_BYTES);
    vq_mma_kernel<<<T / 128, 512, SMEM_BYTES>>>();

    merge_kernel<<<T / 8, 256>>>(x, embed, outq, outi);
}

// round 6
// speedup vs baseline: 1.1390x; 1.1390x over previous
#include <cuda_runtime.h>
#include <cuda_fp16.h>
#include <cstdint>
#include <cfloat>

// Shapes fixed by dataset: T=32768 tokens, K=4096 codes, D=256.
#define T_TOK 32768
#define K_COD 4096
#define D_DIM 256
#define EPS_GAP 0.01f

// Main kernel: CTA = 256 tokens x full K, 256 threads, 8 warps = 4(M) x 2(N),
// warp tile 64 tok x 64 codes. N chunk 128 codes, k-stage 64 (4 HMMA k16),
// 128 stages total (32 chunks x 4 quarters). Single wave: grid 128 <= 148 SMs.
#define A_OFF   0        // A frags fp16: [mtile16][ktile16][lane] uint4 = 128KB
#define B_OFF   131072   // ring: 4 stages x 16KB ([kk4][np8][lane] uint4)
#define ESQ_OFF 196608   // 16KB
#define SMEM_BYTES 212992

__device__ uint4  g_at[(size_t)128 * 8192];   // 16MB packed A fragments
__device__ uint4  g_bt[(size_t)128 * 1024];   // 2MB packed B fragments
__device__ float  g_esq[K_COD];
__device__ float  g_cval[(size_t)T_TOK * 16];
__device__ int    g_cidx[(size_t)T_TOK * 16];

static __device__ __forceinline__ uint32_t smem_u32(const void* p) {
    uint32_t a;
    asm("{ .reg .u64 t; cvta.to.shared.u64 t, %1; cvt.u32.u64 %0, t; }"
        : "=r"(a) : "l"(p));
    return a;
}
static __device__ __forceinline__ void cp16(uint32_t dst, const void* src) {
    asm volatile("cp.async.cg.shared.global [%0], [%1], 16;"
                 :: "r"(dst), "l"(__cvta_generic_to_global(src)) : "memory");
}
#define CP_COMMIT() asm volatile("cp.async.commit_group;" ::: "memory")
#define CP_WAIT(n)  asm volatile("cp.async.wait_group %0;" :: "n"(n) : "memory")

static __device__ __forceinline__ void mma16(float& d0, float& d1, float& d2, float& d3,
                                             uint4 a, uint32_t b0, uint32_t b1) {
    asm volatile(
        "mma.sync.aligned.m16n8k16.row.col.f32.f16.f16.f32 "
        "{%0,%1,%2,%3}, {%4,%5,%6,%7}, {%8,%9}, {%0,%1,%2,%3};"
        : "+f"(d0), "+f"(d1), "+f"(d2), "+f"(d3)
        : "r"(a.x), "r"(a.y), "r"(a.z), "r"(a.w), "r"(b0), "r"(b1));
}
static __device__ __forceinline__ uint32_t h2pack(float a, float b) {
    __half2 h = __floats2half2_rn(a, b);
    return *(uint32_t*)&h;
}

// ---------------------------------------------------------------------------
__global__ void esq_kernel(const float* __restrict__ embed) {
    int k = blockIdx.x * blockDim.x + threadIdx.x;
    const float* row = embed + (size_t)k * D_DIM;
    float s = 0.f;
    for (int d = 0; d < D_DIM; ++d)
        s = __fadd_rn(s, __fmul_rn(row[d], row[d]));
    g_esq[k] = s;
}

// Pack x -> fp16 A fragments (m16n8k16 layout), CTA = 256 tokens.
// unit u = [cta(128)][mtile(16)][ktile(16)][lane(32)] -> uint4 {a0,a1,a2,a3}
// r = mtile*16 + lane/4, c = ktile*16 + (lane%4)*2
__global__ void pack_a_kernel(const float* __restrict__ x) {
    uint32_t u = blockIdx.x * 256 + threadIdx.x;
    int cta = u >> 13, r = u & 8191;
    int mtile = r >> 9, kt = (r >> 5) & 15, lane = r & 31;
    int row = cta * 256 + mtile * 16 + (lane >> 2);
    int col = kt * 16 + (lane & 3) * 2;
    const float* x0 = x + (size_t)row * D_DIM + col;
    const float* x8 = x0 + 8 * D_DIM;
    uint4 q;
    q.x = h2pack(x0[0], x0[1]);
    q.y = h2pack(x8[0], x8[1]);
    q.z = h2pack(x0[8], x0[9]);
    q.w = h2pack(x8[8], x8[9]);
    g_at[u] = q;
}

// Pack embed -> fp16 B fragments, paired for LDS.128.
// unit u = [stage(128)][kk(4)][np(8)][lane(32)]; stage s: nc = s/4, q = s%4.
// codes n = nc*128 + np*16 + {0,8} + lane/4; k = q*64 + kk*16 + (lane%4)*2.
__global__ void pack_b_kernel(const float* __restrict__ embed) {
    uint32_t u = blockIdx.x * 256 + threadIdx.x;
    int s = u >> 10, r = u & 1023;
    int kk = r >> 8, np = (r >> 5) & 7, lane = r & 31;
    int nc = s >> 2, q4 = s & 3;
    int k = q4 * 64 + kk * 16 + (lane & 3) * 2;
    int n0 = nc * 128 + np * 16 + (lane >> 2);
    const float* e0 = embed + (size_t)n0 * D_DIM + k;
    const float* e1 = e0 + 8 * D_DIM;
    uint4 q;
    q.x = h2pack(e0[0], e0[1]);
    q.y = h2pack(e0[8], e0[9]);
    q.z = h2pack(e1[0], e1[1]);
    q.w = h2pack(e1[8], e1[9]);
    g_bt[u] = q;
}

// ---------------------------------------------------------------------------
// Main: fp16 GEMM scores + branchless per-row top-2. 256 threads, warp 64x64.
__global__ __launch_bounds__(256, 1) void vq_mma_kernel() {
    extern __shared__ char sm[];
    const uint32_t sb = smem_u32(sm);
    const int tid = threadIdx.x, lane = tid & 31, wid = tid >> 5;
    const int warpM = wid & 3, warpN = wid >> 2;   // 4 x 2
    const int cta = blockIdx.x;

    // Prologue: A (128KB) + esq (16KB) + B stages 0,1,2 (16KB each)
    {
        const uint4* as = g_at + (size_t)cta * 8192;
#pragma unroll
        for (int i = 0; i < 32; ++i)
            cp16(sb + A_OFF + (uint32_t)(i * 256 + tid) * 16, as + i * 256 + tid);
        const uint4* es = (const uint4*)g_esq;
#pragma unroll
        for (int i = 0; i < 4; ++i)
            cp16(sb + ESQ_OFF + (uint32_t)(i * 256 + tid) * 16, es + i * 256 + tid);
#pragma unroll
        for (int i = 0; i < 4; ++i)
            cp16(sb + B_OFF + (uint32_t)(i * 256 + tid) * 16, g_bt + i * 256 + tid);
        CP_COMMIT();
#pragma unroll
        for (int i = 0; i < 4; ++i)
            cp16(sb + B_OFF + 16384 + (uint32_t)(i * 256 + tid) * 16,
                 g_bt + 1024 + i * 256 + tid);
        CP_COMMIT();
#pragma unroll
        for (int i = 0; i < 4; ++i)
            cp16(sb + B_OFF + 32768 + (uint32_t)(i * 256 + tid) * 16,
                 g_bt + 2048 + i * 256 + tid);
        CP_COMMIT();
    }

    float acc[4][8][4];
#pragma unroll
    for (int mt = 0; mt < 4; ++mt)
#pragma unroll
        for (int nt = 0; nt < 8; ++nt)
#pragma unroll
            for (int c = 0; c < 4; ++c) acc[mt][nt][c] = 0.f;

    // top-2 per token row (8 rows/thread: mt(4) x half(2))
    float t1[8], t2[8];
    int   i1[8], i2[8];
#pragma unroll
    for (int s = 0; s < 8; ++s) {
        t1[s] = -FLT_MAX; t2[s] = -FLT_MAX; i1[s] = 0; i2[s] = 0;
    }

    const float* esm = (const float*)(sm + ESQ_OFF);

    for (int g = 0; g < 128; ++g) {
        CP_WAIT(2);
        __syncthreads();
        if (g + 3 < 128) {
            const uint4* bs = g_bt + (size_t)(g + 3) * 1024;
            uint32_t bd = sb + B_OFF + (uint32_t)((g + 3) & 3) * 16384;
#pragma unroll
            for (int i = 0; i < 4; ++i)
                cp16(bd + (uint32_t)(i * 256 + tid) * 16, bs + i * 256 + tid);
        }
        CP_COMMIT();

        const char* bbuf = sm + B_OFF + (g & 3) * 16384;
#pragma unroll
        for (int kk = 0; kk < 4; ++kk) {
            int ktile = (g & 3) * 4 + kk;
            uint4 a[4];
#pragma unroll
            for (int mt = 0; mt < 4; ++mt)
                a[mt] = *(const uint4*)(sm + A_OFF +
                        (size_t)(((warpM * 4 + mt) * 16 + ktile) * 32 + lane) * 16);
#pragma unroll
            for (int npl = 0; npl < 4; ++npl) {
                uint4 bq = *(const uint4*)(bbuf +
                           (size_t)((kk * 8 + warpN * 4 + npl) * 32 + lane) * 16);
                int ne = 2 * npl, no = 2 * npl + 1;
#pragma unroll
                for (int mt = 0; mt < 4; ++mt) {
                    mma16(acc[mt][ne][0], acc[mt][ne][1], acc[mt][ne][2], acc[mt][ne][3],
                          a[mt], bq.x, bq.y);
                    mma16(acc[mt][no][0], acc[mt][no][1], acc[mt][no][2], acc[mt][no][3],
                          a[mt], bq.z, bq.w);
                }
            }
        }

        if ((g & 3) == 3) {
            // Chunk nc done: score = 2*dot - esq; 16 distinct codes per thread.
            int nc = g >> 2;
            int n0 = nc * 128 + warpN * 64 + (lane & 3) * 2;
            float2 es2[8];
#pragma unroll
            for (int nt = 0; nt < 8; ++nt)
                es2[nt] = *(const float2*)(esm + n0 + (nt >> 1) * 16 + (nt & 1) * 8);
#pragma unroll
            for (int mt = 0; mt < 4; ++mt)
#pragma unroll
                for (int nt = 0; nt < 8; ++nt)
#pragma unroll
                    for (int c = 0; c < 4; ++c) {
                        int n = n0 + (nt >> 1) * 16 + (nt & 1) * 8 + (c & 1);
                        float es = (c & 1) ? es2[nt].y : es2[nt].x;
                        float v = fmaf(2.f, acc[mt][nt][c], -es);
                        acc[mt][nt][c] = 0.f;
                        const int s = mt * 2 + (c >> 1);
                        bool gt1 = v > t1[s];
                        bool gt2 = v > t2[s];
                        i2[s] = gt1 ? i1[s] : (gt2 ? n : i2[s]);
                        t2[s] = gt1 ? t1[s] : (gt2 ? v : t2[s]);
                        i1[s] = gt1 ? n : i1[s];
                        t1[s] = gt1 ? v : t1[s];
                    }
        }
    }

    // Write candidates: 8 sources x top-2 per token = 16.
    // Token row: warpM*64 + mt*16 + h*8 + lane/4; slot: warpN*8 + (lane&3)*2.
#pragma unroll
    for (int s = 0; s < 8; ++s) {
        int mt = s >> 1, h = s & 1;
        int row = warpM * 64 + mt * 16 + h * 8 + (lane >> 2);
        size_t base = ((size_t)cta * 256 + row) * 16 + warpN * 8 + (lane & 3) * 2;
        g_cval[base + 0] = t1[s]; g_cidx[base + 0] = i1[s];
        g_cval[base + 1] = t2[s]; g_cidx[base + 1] = i2[s];
    }
}

// ---------------------------------------------------------------------------
// Merge + rare exact rescore + gather. One warp per token (16 candidates).
__global__ __launch_bounds__(256) void merge_kernel(const float* __restrict__ x,
                                                    const float* __restrict__ embed,
                                                    float* __restrict__ out_q,
                                                    float* __restrict__ out_i) {
    const int lane = threadIdx.x & 31, wid = threadIdx.x >> 5;
    const int t = blockIdx.x * 8 + wid;

    float v = -FLT_MAX;
    int   i = 0x7fffffff;
    if (lane < 16) {
        v = g_cval[(size_t)t * 16 + lane];
        i = g_cidx[(size_t)t * 16 + lane];
    }

    float v1 = v; int i1 = i;
#pragma unroll
    for (int off = 16; off > 0; off >>= 1) {
        float ov = __shfl_xor_sync(0xffffffffu, v1, off);
        int   oi = __shfl_xor_sync(0xffffffffu, i1, off);
        if (ov > v1 || (ov == v1 && oi < i1)) { v1 = ov; i1 = oi; }
    }
    float w = (i == i1) ? -FLT_MAX : v;
#pragma unroll
    for (int off = 16; off > 0; off >>= 1) {
        float ow = __shfl_xor_sync(0xffffffffu, w, off);
        if (ow > w) w = ow;
    }

    int best = i1;
    if (!(v1 - w >= EPS_GAP)) {
        // Exact fp32 rescore of the 16 candidates, ref-faithful rounding.
        const float* xr = x + (size_t)t * D_DIM;
        float p = 0.f;
#pragma unroll
        for (int j = 0; j < 8; ++j) {
            float xv = xr[lane + 32 * j];
            p = __fadd_rn(p, __fmul_rn(xv, xv));
        }
#pragma unroll
        for (int off = 16; off > 0; off >>= 1)
            p = __fadd_rn(p, __shfl_xor_sync(0xffffffffu, p, off));
        const float xsq = p;

        float dn = -FLT_MAX;
        if (lane < 16) {
            const float* er = embed + (size_t)i * D_DIM;
            float dot = 0.f;
            for (int d = 0; d < D_DIM; ++d)
                dot = fmaf(xr[d], er[d], dot);
            float t2v = __fsub_rn(xsq, __fmul_rn(2.f, dot));
            dn = -__fadd_rn(t2v, g_esq[i]);
        }
        float bv = dn; int bi = i;
#pragma unroll
        for (int off = 16; off > 0; off >>= 1) {
            float ov = __shfl_xor_sync(0xffffffffu, bv, off);
            int   oi = __shfl_xor_sync(0xffffffffu, bi, off);
            if (ov > bv || (ov == bv && oi < bi)) { bv = ov; bi = oi; }
        }
        best = bi;
    }

    const float4* src = (const float4*)(embed + (size_t)best * D_DIM);
    float4* dst = (float4*)(out_q + (size_t)t * D_DIM);
    dst[lane] = src[lane];
    dst[lane + 32] = src[lane + 32];
    if (lane == 0 && out_i) out_i[t] = (float)best;
}

// ---------------------------------------------------------------------------
extern "C" void kernel_launch(void* const* d_in, const int* in_sizes, int n_in,
                              void* d_out, int out_size) {
    const float* x     = (const float*)d_in[0];
    const float* embed = (const float*)d_in[1];

    int T = in_sizes[2];  // 32768

    float* outq = (float*)d_out;
    float* outi = nullptr;
    if ((long long)out_size >= (long long)T * D_DIM + T)
        outi = outq + (size_t)T * D_DIM;

    esq_kernel<<<K_COD / 256, 256>>>(embed);
    pack_b_kernel<<<(128 * 1024) / 256, 256>>>(embed);
    pack_a_kernel<<<(128 * 8192) / 256, 256>>>(x);

    cudaFuncSetAttribute(vq_mma_kernel,
                         cudaFuncAttributeMaxDynamicSharedMemorySize, SMEM_BYTES);
    vq_mma_kernel<<<T / 256, 256, SMEM_BYTES>>>();

    merge_kernel<<<T / 8, 256>>>(x, embed, outq, outi);
}